// round 1
// baseline (speedup 1.0000x reference)
#include <cuda_runtime.h>
#include <cstdint>

#define BB 4
#define CC 256
#define HH 256
#define WW 256
#define NROI_MAX 2048
#define FDIM 2304   // 9 * 256
#define DD 256

// ---------------- scratch (device globals: no allocation allowed) ----------
__device__ float g_x [NROI_MAX * FDIM];   // pooled features, bin-major/channel-minor
__device__ float g_h1[NROI_MAX * DD];     // hidden 1 (reused as t1 for each head)
__device__ float g_sh[NROI_MAX * DD];     // shared trunk output
__device__ float g_c2[NROI_MAX * DD];
__device__ float g_i2[NROI_MAX * DD];
__device__ float g_r2[NROI_MAX * DD];

// ---------------- RoIAlignRotated -----------------------------------------
// grid: N blocks, 256 threads (one per channel)
__global__ void roi_kernel(const float* __restrict__ fm,
                           const float* __restrict__ boxes,
                           const int*   __restrict__ bidx,
                           float* __restrict__ xout)
{
    const int n = blockIdx.x;
    const int c = threadIdx.x;

    __shared__ int   s_o[36][4];
    __shared__ float s_w[36][4];

    if (c < 36) {
        const float gw = (float)(102.4 / 256.0);   // grid cell size
        const float bx  = boxes[n*7 + 0];
        const float by  = boxes[n*7 + 1];
        const float rh  = boxes[n*7 + 4] / gw;     // h (in pixels)
        const float rw  = boxes[n*7 + 5] / gw;     // w (in pixels)
        const float ang = boxes[n*7 + 6];

        const float cx = (bx + 51.2f) / gw - 0.5f;
        const float cy = (by + 51.2f) / gw - 0.5f;
        const float ct = cosf(-ang);
        const float st = sinf(-ang);
        const float bin_h = rh / 3.0f;
        const float bin_w = rw / 3.0f;

        const int p  = c;                   // p = ((ph*3+pw)*2+sy)*2+sx
        const int ph = p / 12;
        const int pw = (p / 4) % 3;
        const int sy = (p >> 1) & 1;
        const int sx = p & 1;

        const float yy = -rh * 0.5f + ((float)ph + ((float)sy + 0.5f) * 0.5f) * bin_h;
        const float xx = -rw * 0.5f + ((float)pw + ((float)sx + 0.5f) * 0.5f) * bin_w;

        float y = yy * ct - xx * st + cy;
        float x = yy * st + xx * ct + cx;

        const bool valid = (y > -1.0f) && (y < (float)HH) && (x > -1.0f) && (x < (float)WW);

        y = fminf(fmaxf(y, 0.0f), (float)(HH - 1));
        x = fminf(fmaxf(x, 0.0f), (float)(WW - 1));

        int y0 = min((int)floorf(y), HH - 1);
        int x0 = min((int)floorf(x), WW - 1);
        int y1 = min(y0 + 1, HH - 1);
        int x1 = min(x0 + 1, WW - 1);

        const float ly = y - (float)y0;
        const float lx = x - (float)x0;
        const float hy = 1.0f - ly;
        const float hx = 1.0f - lx;
        const float v  = valid ? 1.0f : 0.0f;

        s_o[p][0] = y0 * WW + x0;
        s_o[p][1] = y0 * WW + x1;
        s_o[p][2] = y1 * WW + x0;
        s_o[p][3] = y1 * WW + x1;
        s_w[p][0] = hy * hx * v;
        s_w[p][1] = hy * lx * v;
        s_w[p][2] = ly * hx * v;
        s_w[p][3] = ly * lx * v;
    }
    __syncthreads();

    const int b = bidx[n];
    const float* __restrict__ base = fm + ((size_t)b * CC + c) * (size_t)(HH * WW);

    float acc[9];
#pragma unroll
    for (int i = 0; i < 9; i++) acc[i] = 0.0f;

#pragma unroll
    for (int p = 0; p < 36; p++) {
        const float vsum =
            s_w[p][0] * __ldg(base + s_o[p][0]) +
            s_w[p][1] * __ldg(base + s_o[p][1]) +
            s_w[p][2] * __ldg(base + s_o[p][2]) +
            s_w[p][3] * __ldg(base + s_o[p][3]);
        acc[p >> 2] += vsum;
    }

    float* __restrict__ xo = xout + (size_t)n * FDIM + c;
#pragma unroll
    for (int i = 0; i < 9; i++)
        xo[i * CC] = acc[i] * 0.25f;
}

// ---------------- fp32 NT GEMM: C[M,N] = act(A[M,K] @ B[N,K]^T) ------------
// 64x64 tile, 256 threads, 4x4 per thread, BK=16. K % 16 == 0, M,N % 64 == 0.
__global__ void gemm_nt(const float* __restrict__ A,
                        const float* __restrict__ B,
                        float* __restrict__ C,
                        int M, int N, int K, int doRelu)
{
    __shared__ float sA[16][64];
    __shared__ float sB[16][64];

    const int tid = threadIdx.x;
    const int m0 = blockIdx.y * 64;
    const int n0 = blockIdx.x * 64;

    const int tx = tid & 15;    // 0..15 -> 4 cols each
    const int ty = tid >> 4;    // 0..15 -> 4 rows each

    const int lr = tid >> 2;          // 0..63 row within tile (loading)
    const int lk = (tid & 3) * 4;     // 0,4,8,12 k-offset (loading)

    const float* __restrict__ Arow = A + (size_t)(m0 + lr) * K + lk;
    const float* __restrict__ Brow = B + (size_t)(n0 + lr) * K + lk;

    float acc[4][4];
#pragma unroll
    for (int i = 0; i < 4; i++)
#pragma unroll
        for (int j = 0; j < 4; j++) acc[i][j] = 0.0f;

    for (int k0 = 0; k0 < K; k0 += 16) {
        const float4 a = *(const float4*)(Arow + k0);
        const float4 b = *(const float4*)(Brow + k0);
        sA[lk + 0][lr] = a.x; sA[lk + 1][lr] = a.y;
        sA[lk + 2][lr] = a.z; sA[lk + 3][lr] = a.w;
        sB[lk + 0][lr] = b.x; sB[lk + 1][lr] = b.y;
        sB[lk + 2][lr] = b.z; sB[lk + 3][lr] = b.w;
        __syncthreads();

#pragma unroll
        for (int k = 0; k < 16; k++) {
            const float4 av = *(const float4*)&sA[k][ty * 4];
            const float4 bv = *(const float4*)&sB[k][tx * 4];
            const float ar[4] = {av.x, av.y, av.z, av.w};
            const float br[4] = {bv.x, bv.y, bv.z, bv.w};
#pragma unroll
            for (int i = 0; i < 4; i++)
#pragma unroll
                for (int j = 0; j < 4; j++)
                    acc[i][j] += ar[i] * br[j];
        }
        __syncthreads();
    }

#pragma unroll
    for (int i = 0; i < 4; i++) {
        const int row = m0 + ty * 4 + i;
        float4 r;
        r.x = acc[i][0]; r.y = acc[i][1]; r.z = acc[i][2]; r.w = acc[i][3];
        if (doRelu) {
            r.x = fmaxf(r.x, 0.0f); r.y = fmaxf(r.y, 0.0f);
            r.z = fmaxf(r.z, 0.0f); r.w = fmaxf(r.w, 0.0f);
        }
        *(float4*)&C[(size_t)row * N + n0 + tx * 4] = r;
    }
}

// ---------------- fused head-final projections -----------------------------
// One warp per roi: computes cls (1), iou (1), reg (7) dots + biases.
__global__ void head_final(const float* __restrict__ c2,
                           const float* __restrict__ i2,
                           const float* __restrict__ r2,
                           const float* __restrict__ wc, const float* __restrict__ bc,
                           const float* __restrict__ wi, const float* __restrict__ bi,
                           const float* __restrict__ wr, const float* __restrict__ br,
                           float* __restrict__ out, int N)
{
    const int warp = (blockIdx.x * blockDim.x + threadIdx.x) >> 5;
    const int lane = threadIdx.x & 31;
    if (warp >= N) return;

    float sc = 0.0f, si = 0.0f;
    float sr[7];
#pragma unroll
    for (int j = 0; j < 7; j++) sr[j] = 0.0f;

    const float* tc = c2 + (size_t)warp * DD;
    const float* ti = i2 + (size_t)warp * DD;
    const float* tr = r2 + (size_t)warp * DD;

#pragma unroll
    for (int kk = 0; kk < DD / 32; kk++) {
        const int k = lane + kk * 32;
        const float vc = tc[k], vi = ti[k], vr = tr[k];
        sc += vc * wc[k];
        si += vi * wi[k];
#pragma unroll
        for (int j = 0; j < 7; j++) sr[j] += vr * wr[j * DD + k];
    }

#pragma unroll
    for (int off = 16; off > 0; off >>= 1) {
        sc += __shfl_down_sync(0xffffffffu, sc, off);
        si += __shfl_down_sync(0xffffffffu, si, off);
#pragma unroll
        for (int j = 0; j < 7; j++) sr[j] += __shfl_down_sync(0xffffffffu, sr[j], off);
    }

    if (lane == 0) {
        out[warp]         = sc + bc[0];
        out[N + warp]     = si + bi[0];
#pragma unroll
        for (int j = 0; j < 7; j++)
            out[2 * N + warp * 7 + j] = sr[j] + br[j];
    }
}

// ---------------- launch ----------------------------------------------------
extern "C" void kernel_launch(void* const* d_in, const int* in_sizes, int n_in,
                              void* d_out, int out_size)
{
    const float* fm    = (const float*)d_in[0];
    const float* boxes = (const float*)d_in[1];
    const int*   bidx  = (const int*)  d_in[2];
    const float* w_sh1 = (const float*)d_in[3];
    const float* w_sh2 = (const float*)d_in[4];
    const float* w_c1  = (const float*)d_in[5];
    const float* w_c2  = (const float*)d_in[6];
    const float* w_c3  = (const float*)d_in[7];
    const float* b_c3  = (const float*)d_in[8];
    const float* w_i1  = (const float*)d_in[9];
    const float* w_i2  = (const float*)d_in[10];
    const float* w_i3  = (const float*)d_in[11];
    const float* b_i3  = (const float*)d_in[12];
    const float* w_r1  = (const float*)d_in[13];
    const float* w_r2  = (const float*)d_in[14];
    const float* w_r3  = (const float*)d_in[15];
    const float* b_r3  = (const float*)d_in[16];
    float* out = (float*)d_out;

    const int N = in_sizes[2];   // number of rois (2048)

    float *px, *ph1, *psh, *pc2, *pi2, *pr2;
    cudaGetSymbolAddress((void**)&px,  g_x);
    cudaGetSymbolAddress((void**)&ph1, g_h1);
    cudaGetSymbolAddress((void**)&psh, g_sh);
    cudaGetSymbolAddress((void**)&pc2, g_c2);
    cudaGetSymbolAddress((void**)&pi2, g_i2);
    cudaGetSymbolAddress((void**)&pr2, g_r2);

    // 1) RoIAlignRotated -> x [N, 2304]
    roi_kernel<<<N, 256>>>(fm, boxes, bidx, px);

    // 2) shared trunk
    {
        dim3 grid(DD / 64, N / 64);
        gemm_nt<<<grid, 256>>>(px,  w_sh1, ph1, N, DD, FDIM, 1);
        gemm_nt<<<grid, 256>>>(ph1, w_sh2, psh, N, DD, DD,   1);

        // 3) heads (t1 reuses g_h1 sequentially)
        gemm_nt<<<grid, 256>>>(psh, w_c1, ph1, N, DD, DD, 1);
        gemm_nt<<<grid, 256>>>(ph1, w_c2, pc2, N, DD, DD, 1);

        gemm_nt<<<grid, 256>>>(psh, w_i1, ph1, N, DD, DD, 1);
        gemm_nt<<<grid, 256>>>(ph1, w_i2, pi2, N, DD, DD, 1);

        gemm_nt<<<grid, 256>>>(psh, w_r1, ph1, N, DD, DD, 1);
        gemm_nt<<<grid, 256>>>(ph1, w_r2, pr2, N, DD, DD, 1);
    }

    // 4) final projections + bias, fused
    {
        const int warps = N;
        const int threads = 256;
        const int blocks = (warps * 32 + threads - 1) / threads;
        head_final<<<blocks, threads>>>(pc2, pi2, pr2,
                                        w_c3, b_c3, w_i3, b_i3, w_r3, b_r3,
                                        out, N);
    }
}

// round 2
// speedup vs baseline: 1.0621x; 1.0621x over previous
#include <cuda_runtime.h>
#include <cstdint>

#define BB 4
#define CC 256
#define HH 256
#define WW 256
#define NROI_MAX 2048
#define FDIM 2304   // 9 * 256
#define DD 256

// ---------------- scratch (device globals: no allocation allowed) ----------
__device__ float g_x  [NROI_MAX * FDIM];  // pooled features
__device__ float g_h1 [NROI_MAX * DD];    // trunk hidden
__device__ float g_sh [NROI_MAX * DD];    // shared trunk output
__device__ float g_t1c[NROI_MAX * DD];
__device__ float g_t1i[NROI_MAX * DD];
__device__ float g_t1r[NROI_MAX * DD];
__device__ float g_c2 [NROI_MAX * DD];
__device__ float g_i2 [NROI_MAX * DD];
__device__ float g_r2 [NROI_MAX * DD];

// ---------------- RoIAlignRotated -----------------------------------------
__global__ void roi_kernel(const float* __restrict__ fm,
                           const float* __restrict__ boxes,
                           const int*   __restrict__ bidx,
                           float* __restrict__ xout)
{
    const int n = blockIdx.x;
    const int c = threadIdx.x;

    __shared__ int   s_o[36][4];
    __shared__ float s_w[36][4];

    if (c < 36) {
        const float gw = (float)(102.4 / 256.0);
        const float bx  = boxes[n*7 + 0];
        const float by  = boxes[n*7 + 1];
        const float rh  = boxes[n*7 + 4] / gw;
        const float rw  = boxes[n*7 + 5] / gw;
        const float ang = boxes[n*7 + 6];

        const float cx = (bx + 51.2f) / gw - 0.5f;
        const float cy = (by + 51.2f) / gw - 0.5f;
        const float ct = cosf(-ang);
        const float st = sinf(-ang);
        const float bin_h = rh / 3.0f;
        const float bin_w = rw / 3.0f;

        const int p  = c;
        const int ph = p / 12;
        const int pw = (p / 4) % 3;
        const int sy = (p >> 1) & 1;
        const int sx = p & 1;

        const float yy = -rh * 0.5f + ((float)ph + ((float)sy + 0.5f) * 0.5f) * bin_h;
        const float xx = -rw * 0.5f + ((float)pw + ((float)sx + 0.5f) * 0.5f) * bin_w;

        float y = yy * ct - xx * st + cy;
        float x = yy * st + xx * ct + cx;

        const bool valid = (y > -1.0f) && (y < (float)HH) && (x > -1.0f) && (x < (float)WW);

        y = fminf(fmaxf(y, 0.0f), (float)(HH - 1));
        x = fminf(fmaxf(x, 0.0f), (float)(WW - 1));

        int y0 = min((int)floorf(y), HH - 1);
        int x0 = min((int)floorf(x), WW - 1);
        int y1 = min(y0 + 1, HH - 1);
        int x1 = min(x0 + 1, WW - 1);

        const float ly = y - (float)y0;
        const float lx = x - (float)x0;
        const float hy = 1.0f - ly;
        const float hx = 1.0f - lx;
        const float v  = valid ? 1.0f : 0.0f;

        s_o[p][0] = y0 * WW + x0;
        s_o[p][1] = y0 * WW + x1;
        s_o[p][2] = y1 * WW + x0;
        s_o[p][3] = y1 * WW + x1;
        s_w[p][0] = hy * hx * v;
        s_w[p][1] = hy * lx * v;
        s_w[p][2] = ly * hx * v;
        s_w[p][3] = ly * lx * v;
    }
    __syncthreads();

    const int b = bidx[n];
    const float* __restrict__ base = fm + ((size_t)b * CC + c) * (size_t)(HH * WW);

    float acc[9];
#pragma unroll
    for (int i = 0; i < 9; i++) acc[i] = 0.0f;

#pragma unroll
    for (int p = 0; p < 36; p++) {
        const float vsum =
            s_w[p][0] * __ldg(base + s_o[p][0]) +
            s_w[p][1] * __ldg(base + s_o[p][1]) +
            s_w[p][2] * __ldg(base + s_o[p][2]) +
            s_w[p][3] * __ldg(base + s_o[p][3]);
        acc[p >> 2] += vsum;
    }

    float* __restrict__ xo = xout + (size_t)n * FDIM + c;
#pragma unroll
    for (int i = 0; i < 9; i++)
        xo[i * CC] = acc[i] * 0.25f;
}

// ---------------- tf32-split tensor-core NT GEMM ---------------------------
// C[M,N] = act(A[M,K] @ B[N,K]^T), both row-major. fp32 accuracy via
// hi/lo tf32 split (3 MMA passes). Tile 64x64, BK=16, 128 threads (4 warps,
// each 32x32). blockIdx.z selects among up to 3 (B, C) pairs (batched heads).
__device__ __forceinline__ void mma_tf32(float* d, const uint32_t* a, const uint32_t* b)
{
    asm volatile(
        "mma.sync.aligned.m16n8k8.row.col.f32.tf32.tf32.f32 "
        "{%0,%1,%2,%3}, {%4,%5,%6,%7}, {%8,%9}, {%0,%1,%2,%3};\n"
        : "+f"(d[0]), "+f"(d[1]), "+f"(d[2]), "+f"(d[3])
        : "r"(a[0]), "r"(a[1]), "r"(a[2]), "r"(a[3]), "r"(b[0]), "r"(b[1]));
}

__device__ __forceinline__ void tf32_split(float f, uint32_t& hi, uint32_t& lo)
{
    uint32_t u = __float_as_uint(f);
    hi = u & 0xffffe000u;
    float l = f - __uint_as_float(hi);
    lo = __float_as_uint(l) & 0xffffe000u;
}

__global__ __launch_bounds__(128)
void gemm_tf32(const float* __restrict__ A,
               const float* __restrict__ B0, const float* __restrict__ B1,
               const float* __restrict__ B2,
               float* __restrict__ C0, float* __restrict__ C1,
               float* __restrict__ C2,
               int M, int N, int K, int doRelu)
{
    const int bz = blockIdx.z;
    const float* __restrict__ B = (bz == 0) ? B0 : ((bz == 1) ? B1 : B2);
    float* __restrict__ C       = (bz == 0) ? C0 : ((bz == 1) ? C1 : C2);

    __shared__ float sA[16][66];
    __shared__ float sB[16][66];

    const int tid  = threadIdx.x;
    const int warp = tid >> 5;
    const int lane = tid & 31;
    const int g    = lane >> 2;   // 0..7
    const int tg   = lane & 3;    // 0..3

    const int m0 = blockIdx.y * 64;
    const int n0 = blockIdx.x * 64;
    const int wm = (warp >> 1) * 32;  // warp m offset in tile
    const int wn = (warp & 1) * 32;   // warp n offset in tile

    float acc[2][4][4];
#pragma unroll
    for (int mt = 0; mt < 2; mt++)
#pragma unroll
        for (int nt = 0; nt < 4; nt++)
#pragma unroll
            for (int i = 0; i < 4; i++) acc[mt][nt][i] = 0.0f;

    for (int k0 = 0; k0 < K; k0 += 16) {
        // ---- load 64x16 A tile and 64x16 B tile (transposed into [k][m]) ----
#pragma unroll
        for (int l = 0; l < 2; l++) {
            const int idx = tid + l * 128;       // 0..255 float4 slots
            const int row = idx >> 2;            // 0..63
            const int kc  = (idx & 3) * 4;       // 0,4,8,12
            const float4 av = *(const float4*)(A + (size_t)(m0 + row) * K + k0 + kc);
            sA[kc + 0][row] = av.x; sA[kc + 1][row] = av.y;
            sA[kc + 2][row] = av.z; sA[kc + 3][row] = av.w;
            const float4 bv = *(const float4*)(B + (size_t)(n0 + row) * K + k0 + kc);
            sB[kc + 0][row] = bv.x; sB[kc + 1][row] = bv.y;
            sB[kc + 2][row] = bv.z; sB[kc + 3][row] = bv.w;
        }
        __syncthreads();

#pragma unroll
        for (int ks = 0; ks < 16; ks += 8) {
            // A fragments (2 m16 tiles), hi/lo
            uint32_t ah[2][4], al[2][4];
#pragma unroll
            for (int mt = 0; mt < 2; mt++) {
                const int r0 = wm + mt * 16 + g;
                const int r1 = r0 + 8;
                tf32_split(sA[ks + tg    ][r0], ah[mt][0], al[mt][0]);
                tf32_split(sA[ks + tg    ][r1], ah[mt][1], al[mt][1]);
                tf32_split(sA[ks + tg + 4][r0], ah[mt][2], al[mt][2]);
                tf32_split(sA[ks + tg + 4][r1], ah[mt][3], al[mt][3]);
            }
            // B fragments (4 n8 tiles), hi/lo
            uint32_t bh[4][2], bl[4][2];
#pragma unroll
            for (int nt = 0; nt < 4; nt++) {
                const int col = wn + nt * 8 + g;
                tf32_split(sB[ks + tg    ][col], bh[nt][0], bl[nt][0]);
                tf32_split(sB[ks + tg + 4][col], bh[nt][1], bl[nt][1]);
            }
#pragma unroll
            for (int mt = 0; mt < 2; mt++)
#pragma unroll
                for (int nt = 0; nt < 4; nt++) {
                    mma_tf32(acc[mt][nt], ah[mt], bh[nt]);
                    mma_tf32(acc[mt][nt], ah[mt], bl[nt]);
                    mma_tf32(acc[mt][nt], al[mt], bh[nt]);
                }
        }
        __syncthreads();
    }

    // ---- epilogue ----
#pragma unroll
    for (int mt = 0; mt < 2; mt++) {
        const int r0 = m0 + wm + mt * 16 + g;
        const int r1 = r0 + 8;
#pragma unroll
        for (int nt = 0; nt < 4; nt++) {
            const int col = n0 + wn + nt * 8 + 2 * tg;
            float2 v0 = make_float2(acc[mt][nt][0], acc[mt][nt][1]);
            float2 v1 = make_float2(acc[mt][nt][2], acc[mt][nt][3]);
            if (doRelu) {
                v0.x = fmaxf(v0.x, 0.0f); v0.y = fmaxf(v0.y, 0.0f);
                v1.x = fmaxf(v1.x, 0.0f); v1.y = fmaxf(v1.y, 0.0f);
            }
            *(float2*)&C[(size_t)r0 * N + col] = v0;
            *(float2*)&C[(size_t)r1 * N + col] = v1;
        }
    }
}

// ---------------- fused head-final projections -----------------------------
__global__ void head_final(const float* __restrict__ c2,
                           const float* __restrict__ i2,
                           const float* __restrict__ r2,
                           const float* __restrict__ wc, const float* __restrict__ bc,
                           const float* __restrict__ wi, const float* __restrict__ bi,
                           const float* __restrict__ wr, const float* __restrict__ br,
                           float* __restrict__ out, int N)
{
    const int warp = (blockIdx.x * blockDim.x + threadIdx.x) >> 5;
    const int lane = threadIdx.x & 31;
    if (warp >= N) return;

    float sc = 0.0f, si = 0.0f;
    float sr[7];
#pragma unroll
    for (int j = 0; j < 7; j++) sr[j] = 0.0f;

    const float* tc = c2 + (size_t)warp * DD;
    const float* ti = i2 + (size_t)warp * DD;
    const float* tr = r2 + (size_t)warp * DD;

#pragma unroll
    for (int kk = 0; kk < DD / 32; kk++) {
        const int k = lane + kk * 32;
        const float vc = tc[k], vi = ti[k], vr = tr[k];
        sc += vc * wc[k];
        si += vi * wi[k];
#pragma unroll
        for (int j = 0; j < 7; j++) sr[j] += vr * wr[j * DD + k];
    }

#pragma unroll
    for (int off = 16; off > 0; off >>= 1) {
        sc += __shfl_down_sync(0xffffffffu, sc, off);
        si += __shfl_down_sync(0xffffffffu, si, off);
#pragma unroll
        for (int j = 0; j < 7; j++) sr[j] += __shfl_down_sync(0xffffffffu, sr[j], off);
    }

    if (lane == 0) {
        out[warp]     = sc + bc[0];
        out[N + warp] = si + bi[0];
#pragma unroll
        for (int j = 0; j < 7; j++)
            out[2 * N + warp * 7 + j] = sr[j] + br[j];
    }
}

// ---------------- launch ----------------------------------------------------
extern "C" void kernel_launch(void* const* d_in, const int* in_sizes, int n_in,
                              void* d_out, int out_size)
{
    const float* fm    = (const float*)d_in[0];
    const float* boxes = (const float*)d_in[1];
    const int*   bidx  = (const int*)  d_in[2];
    const float* w_sh1 = (const float*)d_in[3];
    const float* w_sh2 = (const float*)d_in[4];
    const float* w_c1  = (const float*)d_in[5];
    const float* w_c2  = (const float*)d_in[6];
    const float* w_c3  = (const float*)d_in[7];
    const float* b_c3  = (const float*)d_in[8];
    const float* w_i1  = (const float*)d_in[9];
    const float* w_i2  = (const float*)d_in[10];
    const float* w_i3  = (const float*)d_in[11];
    const float* b_i3  = (const float*)d_in[12];
    const float* w_r1  = (const float*)d_in[13];
    const float* w_r2  = (const float*)d_in[14];
    const float* w_r3  = (const float*)d_in[15];
    const float* b_r3  = (const float*)d_in[16];
    float* out = (float*)d_out;

    const int N = in_sizes[2];   // 2048 rois

    float *px, *ph1, *psh, *pt1c, *pt1i, *pt1r, *pc2, *pi2, *pr2;
    cudaGetSymbolAddress((void**)&px,   g_x);
    cudaGetSymbolAddress((void**)&ph1,  g_h1);
    cudaGetSymbolAddress((void**)&psh,  g_sh);
    cudaGetSymbolAddress((void**)&pt1c, g_t1c);
    cudaGetSymbolAddress((void**)&pt1i, g_t1i);
    cudaGetSymbolAddress((void**)&pt1r, g_t1r);
    cudaGetSymbolAddress((void**)&pc2,  g_c2);
    cudaGetSymbolAddress((void**)&pi2,  g_i2);
    cudaGetSymbolAddress((void**)&pr2,  g_r2);

    // 1) RoIAlignRotated -> x [N, 2304]
    roi_kernel<<<N, 256>>>(fm, boxes, bidx, px);

    // 2) trunk GEMMs (tf32 tensor cores, single z)
    dim3 grid1(DD / 64, N / 64, 1);
    gemm_tf32<<<grid1, 128>>>(px,  w_sh1, w_sh1, w_sh1, ph1, ph1, ph1,
                              N, DD, FDIM, 1);
    gemm_tf32<<<grid1, 128>>>(ph1, w_sh2, w_sh2, w_sh2, psh, psh, psh,
                              N, DD, DD, 1);

    // 3) head layer 1 (batched over z=3)
    dim3 grid3(DD / 64, N / 64, 3);
    gemm_tf32<<<grid3, 128>>>(psh, w_c1, w_i1, w_r1, pt1c, pt1i, pt1r,
                              N, DD, DD, 1);
    // 4) head layer 2 — inputs differ per z, so pass A per-z via trick:
    //    run three single-z launches is wasteful; instead one batched launch
    //    per (A,B,C) triple using a second batched kernel call with A chosen
    //    by aliasing: simplest correct form = 3 small launches back-to-back.
    gemm_tf32<<<grid1, 128>>>(pt1c, w_c2, w_c2, w_c2, pc2, pc2, pc2, N, DD, DD, 1);
    gemm_tf32<<<grid1, 128>>>(pt1i, w_i2, w_i2, w_i2, pi2, pi2, pi2, N, DD, DD, 1);
    gemm_tf32<<<grid1, 128>>>(pt1r, w_r2, w_r2, w_r2, pr2, pr2, pr2, N, DD, DD, 1);

    // 5) final projections + bias, fused
    {
        const int threads = 256;
        const int blocks = (N * 32 + threads - 1) / threads;
        head_final<<<blocks, threads>>>(pc2, pi2, pr2,
                                        w_c3, b_c3, w_i3, b_i3, w_r3, b_r3,
                                        out, N);
    }
}

// round 3
// speedup vs baseline: 1.5017x; 1.4139x over previous
#include <cuda_runtime.h>
#include <cstdint>

#define BB 4
#define CC 256
#define HH 256
#define WW 256
#define NROI_MAX 2048
#define FDIM 2304   // 9 * 256
#define DD 256

// ---------------- scratch (device globals: no allocation allowed) ----------
__device__ float g_fmt[BB * HH * WW * CC];   // NHWC transposed feature map (256 MB)
__device__ float g_x  [NROI_MAX * FDIM];
__device__ float g_h1 [NROI_MAX * DD];
__device__ float g_sh [NROI_MAX * DD];
__device__ float g_t1c[NROI_MAX * DD];
__device__ float g_t1i[NROI_MAX * DD];
__device__ float g_t1r[NROI_MAX * DD];
__device__ float g_c2 [NROI_MAX * DD];
__device__ float g_i2 [NROI_MAX * DD];
__device__ float g_r2 [NROI_MAX * DD];

// ---------------- NCHW -> NHWC transpose -----------------------------------
// Per batch: transpose [C, S] -> [S, C], S = H*W. 32x32 tiles, float4 I/O.
__global__ __launch_bounds__(256)
void transpose_kernel(const float* __restrict__ fm, float* __restrict__ fmt)
{
    __shared__ float tile[32][33];

    const int b  = blockIdx.z;
    const int s0 = blockIdx.x * 32;
    const int c0 = blockIdx.y * 32;
    const int t  = threadIdx.x;

    // load: 32 c-rows x 32 s-cols (float4 along s)
    {
        const int ci = t >> 3;
        const int s4 = (t & 7) * 4;
        const float4 v = *(const float4*)(fm +
            ((size_t)b * CC + (c0 + ci)) * (size_t)(HH * WW) + s0 + s4);
        tile[ci][s4 + 0] = v.x;
        tile[ci][s4 + 1] = v.y;
        tile[ci][s4 + 2] = v.z;
        tile[ci][s4 + 3] = v.w;
    }
    __syncthreads();

    // store: 32 s-rows x 32 c-cols (float4 along c)
    {
        const int si = t >> 3;
        const int c4 = (t & 7) * 4;
        float4 v;
        v.x = tile[c4 + 0][si];
        v.y = tile[c4 + 1][si];
        v.z = tile[c4 + 2][si];
        v.w = tile[c4 + 3][si];
        *(float4*)(fmt + ((size_t)b * (HH * WW) + s0 + si) * (size_t)CC + c0 + c4) = v;
    }
}

// ---------------- RoIAlignRotated (NHWC gather) ----------------------------
// grid: N blocks, 256 threads (one per channel). All loads coalesced.
__global__ __launch_bounds__(256)
void roi_kernel(const float* __restrict__ fmt,
                const float* __restrict__ boxes,
                const int*   __restrict__ bidx,
                float* __restrict__ xout)
{
    const int n = blockIdx.x;
    const int c = threadIdx.x;

    __shared__ int   s_o[36][4];   // NHWC offsets: (y*W+x)*C
    __shared__ float s_w[36][4];

    if (c < 36) {
        const float gw = (float)(102.4 / 256.0);
        const float bx  = boxes[n*7 + 0];
        const float by  = boxes[n*7 + 1];
        const float rh  = boxes[n*7 + 4] / gw;
        const float rw  = boxes[n*7 + 5] / gw;
        const float ang = boxes[n*7 + 6];

        const float cx = (bx + 51.2f) / gw - 0.5f;
        const float cy = (by + 51.2f) / gw - 0.5f;
        const float ct = cosf(-ang);
        const float st = sinf(-ang);
        const float bin_h = rh / 3.0f;
        const float bin_w = rw / 3.0f;

        const int p  = c;
        const int ph = p / 12;
        const int pw = (p / 4) % 3;
        const int sy = (p >> 1) & 1;
        const int sx = p & 1;

        const float yy = -rh * 0.5f + ((float)ph + ((float)sy + 0.5f) * 0.5f) * bin_h;
        const float xx = -rw * 0.5f + ((float)pw + ((float)sx + 0.5f) * 0.5f) * bin_w;

        float y = yy * ct - xx * st + cy;
        float x = yy * st + xx * ct + cx;

        const bool valid = (y > -1.0f) && (y < (float)HH) && (x > -1.0f) && (x < (float)WW);

        y = fminf(fmaxf(y, 0.0f), (float)(HH - 1));
        x = fminf(fmaxf(x, 0.0f), (float)(WW - 1));

        int y0 = min((int)floorf(y), HH - 1);
        int x0 = min((int)floorf(x), WW - 1);
        int y1 = min(y0 + 1, HH - 1);
        int x1 = min(x0 + 1, WW - 1);

        const float ly = y - (float)y0;
        const float lx = x - (float)x0;
        const float hy = 1.0f - ly;
        const float hx = 1.0f - lx;
        const float v  = valid ? 1.0f : 0.0f;

        s_o[p][0] = (y0 * WW + x0) * CC;
        s_o[p][1] = (y0 * WW + x1) * CC;
        s_o[p][2] = (y1 * WW + x0) * CC;
        s_o[p][3] = (y1 * WW + x1) * CC;
        s_w[p][0] = hy * hx * v;
        s_w[p][1] = hy * lx * v;
        s_w[p][2] = ly * hx * v;
        s_w[p][3] = ly * lx * v;
    }
    __syncthreads();

    const int b = bidx[n];
    const float* __restrict__ base = fmt + (size_t)b * (HH * WW) * CC + c;

    float acc[9];
#pragma unroll
    for (int i = 0; i < 9; i++) acc[i] = 0.0f;

#pragma unroll
    for (int p = 0; p < 36; p++) {
        const float vsum =
            s_w[p][0] * __ldg(base + s_o[p][0]) +
            s_w[p][1] * __ldg(base + s_o[p][1]) +
            s_w[p][2] * __ldg(base + s_o[p][2]) +
            s_w[p][3] * __ldg(base + s_o[p][3]);
        acc[p >> 2] += vsum;
    }

    float* __restrict__ xo = xout + (size_t)n * FDIM + c;
#pragma unroll
    for (int i = 0; i < 9; i++)
        xo[i * CC] = acc[i] * 0.25f;
}

// ---------------- tf32-split tensor-core NT GEMM ---------------------------
// C[M,N] = act(A[M,K] @ B[N,K]^T). hi/lo tf32 split (3 MMA passes).
// Tile 64x64, BK=16, 128 threads. blockIdx.z selects (A,B,C) triple.
__device__ __forceinline__ void mma_tf32(float* d, const uint32_t* a, const uint32_t* b)
{
    asm volatile(
        "mma.sync.aligned.m16n8k8.row.col.f32.tf32.tf32.f32 "
        "{%0,%1,%2,%3}, {%4,%5,%6,%7}, {%8,%9}, {%0,%1,%2,%3};\n"
        : "+f"(d[0]), "+f"(d[1]), "+f"(d[2]), "+f"(d[3])
        : "r"(a[0]), "r"(a[1]), "r"(a[2]), "r"(a[3]), "r"(b[0]), "r"(b[1]));
}

__device__ __forceinline__ void tf32_split(float f, uint32_t& hi, uint32_t& lo)
{
    uint32_t u = __float_as_uint(f);
    hi = u & 0xffffe000u;
    float l = f - __uint_as_float(hi);
    lo = __float_as_uint(l) & 0xffffe000u;
}

__global__ __launch_bounds__(128)
void gemm_tf32(const float* __restrict__ A0, const float* __restrict__ A1,
               const float* __restrict__ A2,
               const float* __restrict__ B0, const float* __restrict__ B1,
               const float* __restrict__ B2,
               float* __restrict__ C0, float* __restrict__ C1,
               float* __restrict__ C2,
               int M, int N, int K, int doRelu)
{
    const int bz = blockIdx.z;
    const float* __restrict__ A = (bz == 0) ? A0 : ((bz == 1) ? A1 : A2);
    const float* __restrict__ B = (bz == 0) ? B0 : ((bz == 1) ? B1 : B2);
    float* __restrict__ C       = (bz == 0) ? C0 : ((bz == 1) ? C1 : C2);

    __shared__ float sA[16][66];
    __shared__ float sB[16][66];

    const int tid  = threadIdx.x;
    const int warp = tid >> 5;
    const int lane = tid & 31;
    const int g    = lane >> 2;
    const int tg   = lane & 3;

    const int m0 = blockIdx.y * 64;
    const int n0 = blockIdx.x * 64;
    const int wm = (warp >> 1) * 32;
    const int wn = (warp & 1) * 32;

    float acc[2][4][4];
#pragma unroll
    for (int mt = 0; mt < 2; mt++)
#pragma unroll
        for (int nt = 0; nt < 4; nt++)
#pragma unroll
            for (int i = 0; i < 4; i++) acc[mt][nt][i] = 0.0f;

    for (int k0 = 0; k0 < K; k0 += 16) {
#pragma unroll
        for (int l = 0; l < 2; l++) {
            const int idx = tid + l * 128;
            const int row = idx >> 2;
            const int kc  = (idx & 3) * 4;
            const float4 av = *(const float4*)(A + (size_t)(m0 + row) * K + k0 + kc);
            sA[kc + 0][row] = av.x; sA[kc + 1][row] = av.y;
            sA[kc + 2][row] = av.z; sA[kc + 3][row] = av.w;
            const float4 bv = *(const float4*)(B + (size_t)(n0 + row) * K + k0 + kc);
            sB[kc + 0][row] = bv.x; sB[kc + 1][row] = bv.y;
            sB[kc + 2][row] = bv.z; sB[kc + 3][row] = bv.w;
        }
        __syncthreads();

#pragma unroll
        for (int ks = 0; ks < 16; ks += 8) {
            uint32_t ah[2][4], al[2][4];
#pragma unroll
            for (int mt = 0; mt < 2; mt++) {
                const int r0 = wm + mt * 16 + g;
                const int r1 = r0 + 8;
                tf32_split(sA[ks + tg    ][r0], ah[mt][0], al[mt][0]);
                tf32_split(sA[ks + tg    ][r1], ah[mt][1], al[mt][1]);
                tf32_split(sA[ks + tg + 4][r0], ah[mt][2], al[mt][2]);
                tf32_split(sA[ks + tg + 4][r1], ah[mt][3], al[mt][3]);
            }
            uint32_t bh[4][2], bl[4][2];
#pragma unroll
            for (int nt = 0; nt < 4; nt++) {
                const int col = wn + nt * 8 + g;
                tf32_split(sB[ks + tg    ][col], bh[nt][0], bl[nt][0]);
                tf32_split(sB[ks + tg + 4][col], bh[nt][1], bl[nt][1]);
            }
#pragma unroll
            for (int mt = 0; mt < 2; mt++)
#pragma unroll
                for (int nt = 0; nt < 4; nt++) {
                    mma_tf32(acc[mt][nt], ah[mt], bh[nt]);
                    mma_tf32(acc[mt][nt], ah[mt], bl[nt]);
                    mma_tf32(acc[mt][nt], al[mt], bh[nt]);
                }
        }
        __syncthreads();
    }

#pragma unroll
    for (int mt = 0; mt < 2; mt++) {
        const int r0 = m0 + wm + mt * 16 + g;
        const int r1 = r0 + 8;
#pragma unroll
        for (int nt = 0; nt < 4; nt++) {
            const int col = n0 + wn + nt * 8 + 2 * tg;
            float2 v0 = make_float2(acc[mt][nt][0], acc[mt][nt][1]);
            float2 v1 = make_float2(acc[mt][nt][2], acc[mt][nt][3]);
            if (doRelu) {
                v0.x = fmaxf(v0.x, 0.0f); v0.y = fmaxf(v0.y, 0.0f);
                v1.x = fmaxf(v1.x, 0.0f); v1.y = fmaxf(v1.y, 0.0f);
            }
            *(float2*)&C[(size_t)r0 * N + col] = v0;
            *(float2*)&C[(size_t)r1 * N + col] = v1;
        }
    }
}

// ---------------- fused head-final projections -----------------------------
__global__ void head_final(const float* __restrict__ c2,
                           const float* __restrict__ i2,
                           const float* __restrict__ r2,
                           const float* __restrict__ wc, const float* __restrict__ bc,
                           const float* __restrict__ wi, const float* __restrict__ bi,
                           const float* __restrict__ wr, const float* __restrict__ br,
                           float* __restrict__ out, int N)
{
    const int warp = (blockIdx.x * blockDim.x + threadIdx.x) >> 5;
    const int lane = threadIdx.x & 31;
    if (warp >= N) return;

    float sc = 0.0f, si = 0.0f;
    float sr[7];
#pragma unroll
    for (int j = 0; j < 7; j++) sr[j] = 0.0f;

    const float* tc = c2 + (size_t)warp * DD;
    const float* ti = i2 + (size_t)warp * DD;
    const float* tr = r2 + (size_t)warp * DD;

#pragma unroll
    for (int kk = 0; kk < DD / 32; kk++) {
        const int k = lane + kk * 32;
        const float vc = tc[k], vi = ti[k], vr = tr[k];
        sc += vc * wc[k];
        si += vi * wi[k];
#pragma unroll
        for (int j = 0; j < 7; j++) sr[j] += vr * wr[j * DD + k];
    }

#pragma unroll
    for (int off = 16; off > 0; off >>= 1) {
        sc += __shfl_down_sync(0xffffffffu, sc, off);
        si += __shfl_down_sync(0xffffffffu, si, off);
#pragma unroll
        for (int j = 0; j < 7; j++) sr[j] += __shfl_down_sync(0xffffffffu, sr[j], off);
    }

    if (lane == 0) {
        out[warp]     = sc + bc[0];
        out[N + warp] = si + bi[0];
#pragma unroll
        for (int j = 0; j < 7; j++)
            out[2 * N + warp * 7 + j] = sr[j] + br[j];
    }
}

// ---------------- launch ----------------------------------------------------
extern "C" void kernel_launch(void* const* d_in, const int* in_sizes, int n_in,
                              void* d_out, int out_size)
{
    const float* fm    = (const float*)d_in[0];
    const float* boxes = (const float*)d_in[1];
    const int*   bidx  = (const int*)  d_in[2];
    const float* w_sh1 = (const float*)d_in[3];
    const float* w_sh2 = (const float*)d_in[4];
    const float* w_c1  = (const float*)d_in[5];
    const float* w_c2  = (const float*)d_in[6];
    const float* w_c3  = (const float*)d_in[7];
    const float* b_c3  = (const float*)d_in[8];
    const float* w_i1  = (const float*)d_in[9];
    const float* w_i2  = (const float*)d_in[10];
    const float* w_i3  = (const float*)d_in[11];
    const float* b_i3  = (const float*)d_in[12];
    const float* w_r1  = (const float*)d_in[13];
    const float* w_r2  = (const float*)d_in[14];
    const float* w_r3  = (const float*)d_in[15];
    const float* b_r3  = (const float*)d_in[16];
    float* out = (float*)d_out;

    const int N = in_sizes[2];   // 2048 rois

    float *pfmt, *px, *ph1, *psh, *pt1c, *pt1i, *pt1r, *pc2, *pi2, *pr2;
    cudaGetSymbolAddress((void**)&pfmt, g_fmt);
    cudaGetSymbolAddress((void**)&px,   g_x);
    cudaGetSymbolAddress((void**)&ph1,  g_h1);
    cudaGetSymbolAddress((void**)&psh,  g_sh);
    cudaGetSymbolAddress((void**)&pt1c, g_t1c);
    cudaGetSymbolAddress((void**)&pt1i, g_t1i);
    cudaGetSymbolAddress((void**)&pt1r, g_t1r);
    cudaGetSymbolAddress((void**)&pc2,  g_c2);
    cudaGetSymbolAddress((void**)&pi2,  g_i2);
    cudaGetSymbolAddress((void**)&pr2,  g_r2);

    // 0) NCHW -> NHWC
    {
        dim3 grid(HH * WW / 32, CC / 32, BB);
        transpose_kernel<<<grid, 256>>>(fm, pfmt);
    }

    // 1) RoIAlignRotated (coalesced NHWC gather) -> x [N, 2304]
    roi_kernel<<<N, 256>>>(pfmt, boxes, bidx, px);

    // 2) trunk GEMMs
    dim3 grid1(DD / 64, N / 64, 1);
    gemm_tf32<<<grid1, 128>>>(px, px, px, w_sh1, w_sh1, w_sh1,
                              ph1, ph1, ph1, N, DD, FDIM, 1);
    gemm_tf32<<<grid1, 128>>>(ph1, ph1, ph1, w_sh2, w_sh2, w_sh2,
                              psh, psh, psh, N, DD, DD, 1);

    // 3) heads: layer 1 and layer 2 each batched over z=3
    dim3 grid3(DD / 64, N / 64, 3);
    gemm_tf32<<<grid3, 128>>>(psh, psh, psh, w_c1, w_i1, w_r1,
                              pt1c, pt1i, pt1r, N, DD, DD, 1);
    gemm_tf32<<<grid3, 128>>>(pt1c, pt1i, pt1r, w_c2, w_i2, w_r2,
                              pc2, pi2, pr2, N, DD, DD, 1);

    // 4) final projections + bias, fused
    {
        const int threads = 256;
        const int blocks = (N * 32 + threads - 1) / threads;
        head_final<<<blocks, threads>>>(pc2, pi2, pr2,
                                        w_c3, b_c3, w_i3, b_i3, w_r3, b_r3,
                                        out, N);
    }
}

// round 4
// speedup vs baseline: 2.2332x; 1.4872x over previous
#include <cuda_runtime.h>
#include <cstdint>

#define BB 4
#define CC 256
#define HH 256
#define WW 256
#define NROI_MAX 2048
#define FDIM 2304
#define DD 256

// ---------------- scratch ----------------------------------------------------
__device__ float g_fmt[BB * HH * WW * CC];
__device__ float g_x  [NROI_MAX * FDIM];
__device__ float g_h1 [NROI_MAX * DD];
__device__ float g_sh [NROI_MAX * DD];
__device__ float g_t1c[NROI_MAX * DD];
__device__ float g_t1i[NROI_MAX * DD];
__device__ float g_t1r[NROI_MAX * DD];
__device__ float g_c2 [NROI_MAX * DD];
__device__ float g_i2 [NROI_MAX * DD];
__device__ float g_r2 [NROI_MAX * DD];

// ---------------- NCHW -> NHWC transpose (32c x 64s per block) --------------
__global__ __launch_bounds__(256)
void transpose_kernel(const float* __restrict__ fm, float* __restrict__ fmt)
{
    __shared__ float tile[32][65];

    const int b  = blockIdx.z;
    const int s0 = blockIdx.x * 64;
    const int c0 = blockIdx.y * 32;
    const int t  = threadIdx.x;

#pragma unroll
    for (int l = 0; l < 2; l++) {
        const int slot = t + l * 256;
        const int ci = slot >> 4;          // 0..31
        const int s4 = (slot & 15) * 4;    // 0..60
        const float4 v = *(const float4*)(fm +
            ((size_t)b * CC + (c0 + ci)) * (size_t)(HH * WW) + s0 + s4);
        tile[ci][s4 + 0] = v.x;
        tile[ci][s4 + 1] = v.y;
        tile[ci][s4 + 2] = v.z;
        tile[ci][s4 + 3] = v.w;
    }
    __syncthreads();

#pragma unroll
    for (int l = 0; l < 2; l++) {
        const int slot = t + l * 256;
        const int si = slot >> 3;          // 0..63
        const int c4 = (slot & 7) * 4;     // 0..28
        float4 v;
        v.x = tile[c4 + 0][si];
        v.y = tile[c4 + 1][si];
        v.z = tile[c4 + 2][si];
        v.w = tile[c4 + 3][si];
        *(float4*)(fmt + ((size_t)b * (HH * WW) + s0 + si) * (size_t)CC + c0 + c4) = v;
    }
}

// ---------------- RoIAlignRotated (NHWC gather) ----------------------------
__global__ __launch_bounds__(256)
void roi_kernel(const float* __restrict__ fmt,
                const float* __restrict__ boxes,
                const int*   __restrict__ bidx,
                float* __restrict__ xout)
{
    const int n = blockIdx.x;
    const int c = threadIdx.x;

    __shared__ int   s_o[36][4];
    __shared__ float s_w[36][4];

    if (c < 36) {
        const float gw = (float)(102.4 / 256.0);
        const float bx  = boxes[n*7 + 0];
        const float by  = boxes[n*7 + 1];
        const float rh  = boxes[n*7 + 4] / gw;
        const float rw  = boxes[n*7 + 5] / gw;
        const float ang = boxes[n*7 + 6];

        const float cx = (bx + 51.2f) / gw - 0.5f;
        const float cy = (by + 51.2f) / gw - 0.5f;
        const float ct = cosf(-ang);
        const float st = sinf(-ang);
        const float bin_h = rh / 3.0f;
        const float bin_w = rw / 3.0f;

        const int p  = c;
        const int ph = p / 12;
        const int pw = (p / 4) % 3;
        const int sy = (p >> 1) & 1;
        const int sx = p & 1;

        const float yy = -rh * 0.5f + ((float)ph + ((float)sy + 0.5f) * 0.5f) * bin_h;
        const float xx = -rw * 0.5f + ((float)pw + ((float)sx + 0.5f) * 0.5f) * bin_w;

        float y = yy * ct - xx * st + cy;
        float x = yy * st + xx * ct + cx;

        const bool valid = (y > -1.0f) && (y < (float)HH) && (x > -1.0f) && (x < (float)WW);

        y = fminf(fmaxf(y, 0.0f), (float)(HH - 1));
        x = fminf(fmaxf(x, 0.0f), (float)(WW - 1));

        int y0 = min((int)floorf(y), HH - 1);
        int x0 = min((int)floorf(x), WW - 1);
        int y1 = min(y0 + 1, HH - 1);
        int x1 = min(x0 + 1, WW - 1);

        const float ly = y - (float)y0;
        const float lx = x - (float)x0;
        const float hy = 1.0f - ly;
        const float hx = 1.0f - lx;
        const float v  = valid ? 1.0f : 0.0f;

        s_o[p][0] = (y0 * WW + x0) * CC;
        s_o[p][1] = (y0 * WW + x1) * CC;
        s_o[p][2] = (y1 * WW + x0) * CC;
        s_o[p][3] = (y1 * WW + x1) * CC;
        s_w[p][0] = hy * hx * v;
        s_w[p][1] = hy * lx * v;
        s_w[p][2] = ly * hx * v;
        s_w[p][3] = ly * lx * v;
    }
    __syncthreads();

    const int b = bidx[n];
    const float* __restrict__ base = fmt + (size_t)b * (HH * WW) * CC + c;

    float acc[9];
#pragma unroll
    for (int i = 0; i < 9; i++) acc[i] = 0.0f;

#pragma unroll
    for (int p = 0; p < 36; p++) {
        const float vsum =
            s_w[p][0] * __ldg(base + s_o[p][0]) +
            s_w[p][1] * __ldg(base + s_o[p][1]) +
            s_w[p][2] * __ldg(base + s_o[p][2]) +
            s_w[p][3] * __ldg(base + s_o[p][3]);
        acc[p >> 2] += vsum;
    }

    float* __restrict__ xo = xout + (size_t)n * FDIM + c;
#pragma unroll
    for (int i = 0; i < 9; i++)
        xo[i * CC] = acc[i] * 0.25f;
}

// ---------------- tf32-split tensor-core NT GEMM, cp.async double-buffered --
// C[M,N] = act(A[M,K] @ B[N,K]^T). 64x64 tile, BK=32, 256 threads (8 warps,
// warp tile 16m x 32n). blockIdx.z picks (A,B,C) triple. K % 32 == 0.
__device__ __forceinline__ void mma_tf32(float* d, const uint32_t* a, const uint32_t* b)
{
    asm volatile(
        "mma.sync.aligned.m16n8k8.row.col.f32.tf32.tf32.f32 "
        "{%0,%1,%2,%3}, {%4,%5,%6,%7}, {%8,%9}, {%0,%1,%2,%3};\n"
        : "+f"(d[0]), "+f"(d[1]), "+f"(d[2]), "+f"(d[3])
        : "r"(a[0]), "r"(a[1]), "r"(a[2]), "r"(a[3]), "r"(b[0]), "r"(b[1]));
}

__device__ __forceinline__ void tf32_split(float f, uint32_t& hi, uint32_t& lo)
{
    uint32_t u = __float_as_uint(f);
    hi = u & 0xffffe000u;
    float l = f - __uint_as_float(hi);
    lo = __float_as_uint(l) & 0xffffe000u;
}

__device__ __forceinline__ void cp_async16(uint32_t smem_addr, const void* gptr)
{
    asm volatile("cp.async.cg.shared.global [%0], [%1], 16;\n"
                 :: "r"(smem_addr), "l"(gptr));
}

#define SKP 36   // 32 + 4 pad: conflict-free fragment reads

__global__ __launch_bounds__(256)
void gemm_tf32(const float* __restrict__ A0, const float* __restrict__ A1,
               const float* __restrict__ A2,
               const float* __restrict__ B0, const float* __restrict__ B1,
               const float* __restrict__ B2,
               float* __restrict__ C0, float* __restrict__ C1,
               float* __restrict__ C2,
               int M, int N, int K, int doRelu)
{
    const int bz = blockIdx.z;
    const float* __restrict__ A = (bz == 0) ? A0 : ((bz == 1) ? A1 : A2);
    const float* __restrict__ B = (bz == 0) ? B0 : ((bz == 1) ? B1 : B2);
    float* __restrict__ C       = (bz == 0) ? C0 : ((bz == 1) ? C1 : C2);

    __shared__ float sA[2][64][SKP];
    __shared__ float sB[2][64][SKP];

    const int tid  = threadIdx.x;
    const int warp = tid >> 5;
    const int lane = tid & 31;
    const int g    = lane >> 2;   // 0..7
    const int tg   = lane & 3;    // 0..3

    const int m0 = blockIdx.y * 64;
    const int n0 = blockIdx.x * 64;
    const int wm = (warp >> 1) * 16;   // 0,16,32,48
    const int wn = (warp & 1) * 32;    // 0,32

    // loader mapping: 2 float4 slots per thread per matrix per stage
    const int lrow = tid >> 3;            // 0..31  (row block 0) / +32 for slot 2
    const int lk4  = (tid & 7) * 4;       // 0,4,...,28

    float acc[4][4];
#pragma unroll
    for (int nt = 0; nt < 4; nt++)
#pragma unroll
        for (int i = 0; i < 4; i++) acc[nt][i] = 0.0f;

    const int T = K >> 5;   // BK=32 steps

    // prologue: stage 0
    {
        const float* aptr0 = A + (size_t)(m0 + lrow) * K + lk4;
        const float* aptr1 = A + (size_t)(m0 + lrow + 32) * K + lk4;
        const float* bptr0 = B + (size_t)(n0 + lrow) * K + lk4;
        const float* bptr1 = B + (size_t)(n0 + lrow + 32) * K + lk4;
        cp_async16((uint32_t)__cvta_generic_to_shared(&sA[0][lrow     ][lk4]), aptr0);
        cp_async16((uint32_t)__cvta_generic_to_shared(&sA[0][lrow + 32][lk4]), aptr1);
        cp_async16((uint32_t)__cvta_generic_to_shared(&sB[0][lrow     ][lk4]), bptr0);
        cp_async16((uint32_t)__cvta_generic_to_shared(&sB[0][lrow + 32][lk4]), bptr1);
        asm volatile("cp.async.commit_group;\n");
    }

    for (int kt = 0; kt < T; kt++) {
        const int buf = kt & 1;
        if (kt + 1 < T) {
            const int nb = (kt + 1) & 1;
            const int ko = (kt + 1) << 5;
            cp_async16((uint32_t)__cvta_generic_to_shared(&sA[nb][lrow     ][lk4]),
                       A + (size_t)(m0 + lrow) * K + ko + lk4);
            cp_async16((uint32_t)__cvta_generic_to_shared(&sA[nb][lrow + 32][lk4]),
                       A + (size_t)(m0 + lrow + 32) * K + ko + lk4);
            cp_async16((uint32_t)__cvta_generic_to_shared(&sB[nb][lrow     ][lk4]),
                       B + (size_t)(n0 + lrow) * K + ko + lk4);
            cp_async16((uint32_t)__cvta_generic_to_shared(&sB[nb][lrow + 32][lk4]),
                       B + (size_t)(n0 + lrow + 32) * K + ko + lk4);
            asm volatile("cp.async.commit_group;\n");
            asm volatile("cp.async.wait_group 1;\n");
        } else {
            asm volatile("cp.async.wait_group 0;\n");
        }
        __syncthreads();

#pragma unroll
        for (int ks = 0; ks < 32; ks += 8) {
            uint32_t ah[4], al[4];
            tf32_split(sA[buf][wm + g    ][ks + tg    ], ah[0], al[0]);
            tf32_split(sA[buf][wm + g + 8][ks + tg    ], ah[1], al[1]);
            tf32_split(sA[buf][wm + g    ][ks + tg + 4], ah[2], al[2]);
            tf32_split(sA[buf][wm + g + 8][ks + tg + 4], ah[3], al[3]);

            uint32_t bh[4][2], bl[4][2];
#pragma unroll
            for (int nt = 0; nt < 4; nt++) {
                const int col = wn + nt * 8 + g;
                tf32_split(sB[buf][col][ks + tg    ], bh[nt][0], bl[nt][0]);
                tf32_split(sB[buf][col][ks + tg + 4], bh[nt][1], bl[nt][1]);
            }
#pragma unroll
            for (int nt = 0; nt < 4; nt++) {
                mma_tf32(acc[nt], ah, bh[nt]);
                mma_tf32(acc[nt], ah, bl[nt]);
                mma_tf32(acc[nt], al, bh[nt]);
            }
        }
        __syncthreads();
    }

    // epilogue
    const int r0 = m0 + wm + g;
    const int r1 = r0 + 8;
#pragma unroll
    for (int nt = 0; nt < 4; nt++) {
        const int col = n0 + wn + nt * 8 + 2 * tg;
        float2 v0 = make_float2(acc[nt][0], acc[nt][1]);
        float2 v1 = make_float2(acc[nt][2], acc[nt][3]);
        if (doRelu) {
            v0.x = fmaxf(v0.x, 0.0f); v0.y = fmaxf(v0.y, 0.0f);
            v1.x = fmaxf(v1.x, 0.0f); v1.y = fmaxf(v1.y, 0.0f);
        }
        *(float2*)&C[(size_t)r0 * N + col] = v0;
        *(float2*)&C[(size_t)r1 * N + col] = v1;
    }
}

// ---------------- fused head-final projections -----------------------------
__global__ void head_final(const float* __restrict__ c2,
                           const float* __restrict__ i2,
                           const float* __restrict__ r2,
                           const float* __restrict__ wc, const float* __restrict__ bc,
                           const float* __restrict__ wi, const float* __restrict__ bi,
                           const float* __restrict__ wr, const float* __restrict__ br,
                           float* __restrict__ out, int N)
{
    const int warp = (blockIdx.x * blockDim.x + threadIdx.x) >> 5;
    const int lane = threadIdx.x & 31;
    if (warp >= N) return;

    float sc = 0.0f, si = 0.0f;
    float sr[7];
#pragma unroll
    for (int j = 0; j < 7; j++) sr[j] = 0.0f;

    const float* tc = c2 + (size_t)warp * DD;
    const float* ti = i2 + (size_t)warp * DD;
    const float* tr = r2 + (size_t)warp * DD;

#pragma unroll
    for (int kk = 0; kk < DD / 32; kk++) {
        const int k = lane + kk * 32;
        const float vc = tc[k], vi = ti[k], vr = tr[k];
        sc += vc * wc[k];
        si += vi * wi[k];
#pragma unroll
        for (int j = 0; j < 7; j++) sr[j] += vr * wr[j * DD + k];
    }

#pragma unroll
    for (int off = 16; off > 0; off >>= 1) {
        sc += __shfl_down_sync(0xffffffffu, sc, off);
        si += __shfl_down_sync(0xffffffffu, si, off);
#pragma unroll
        for (int j = 0; j < 7; j++) sr[j] += __shfl_down_sync(0xffffffffu, sr[j], off);
    }

    if (lane == 0) {
        out[warp]     = sc + bc[0];
        out[N + warp] = si + bi[0];
#pragma unroll
        for (int j = 0; j < 7; j++)
            out[2 * N + warp * 7 + j] = sr[j] + br[j];
    }
}

// ---------------- launch ----------------------------------------------------
extern "C" void kernel_launch(void* const* d_in, const int* in_sizes, int n_in,
                              void* d_out, int out_size)
{
    const float* fm    = (const float*)d_in[0];
    const float* boxes = (const float*)d_in[1];
    const int*   bidx  = (const int*)  d_in[2];
    const float* w_sh1 = (const float*)d_in[3];
    const float* w_sh2 = (const float*)d_in[4];
    const float* w_c1  = (const float*)d_in[5];
    const float* w_c2  = (const float*)d_in[6];
    const float* w_c3  = (const float*)d_in[7];
    const float* b_c3  = (const float*)d_in[8];
    const float* w_i1  = (const float*)d_in[9];
    const float* w_i2  = (const float*)d_in[10];
    const float* w_i3  = (const float*)d_in[11];
    const float* b_i3  = (const float*)d_in[12];
    const float* w_r1  = (const float*)d_in[13];
    const float* w_r2  = (const float*)d_in[14];
    const float* w_r3  = (const float*)d_in[15];
    const float* b_r3  = (const float*)d_in[16];
    float* out = (float*)d_out;

    const int N = in_sizes[2];

    float *pfmt, *px, *ph1, *psh, *pt1c, *pt1i, *pt1r, *pc2, *pi2, *pr2;
    cudaGetSymbolAddress((void**)&pfmt, g_fmt);
    cudaGetSymbolAddress((void**)&px,   g_x);
    cudaGetSymbolAddress((void**)&ph1,  g_h1);
    cudaGetSymbolAddress((void**)&psh,  g_sh);
    cudaGetSymbolAddress((void**)&pt1c, g_t1c);
    cudaGetSymbolAddress((void**)&pt1i, g_t1i);
    cudaGetSymbolAddress((void**)&pt1r, g_t1r);
    cudaGetSymbolAddress((void**)&pc2,  g_c2);
    cudaGetSymbolAddress((void**)&pi2,  g_i2);
    cudaGetSymbolAddress((void**)&pr2,  g_r2);

    // 0) NCHW -> NHWC
    {
        dim3 grid(HH * WW / 64, CC / 32, BB);
        transpose_kernel<<<grid, 256>>>(fm, pfmt);
    }

    // 1) RoIAlignRotated -> x [N, 2304]
    roi_kernel<<<N, 256>>>(pfmt, boxes, bidx, px);

    // 2) trunk GEMMs
    dim3 grid1(DD / 64, N / 64, 1);
    gemm_tf32<<<grid1, 256>>>(px, px, px, w_sh1, w_sh1, w_sh1,
                              ph1, ph1, ph1, N, DD, FDIM, 1);
    gemm_tf32<<<grid1, 256>>>(ph1, ph1, ph1, w_sh2, w_sh2, w_sh2,
                              psh, psh, psh, N, DD, DD, 1);

    // 3) heads, batched over z
    dim3 grid3(DD / 64, N / 64, 3);
    gemm_tf32<<<grid3, 256>>>(psh, psh, psh, w_c1, w_i1, w_r1,
                              pt1c, pt1i, pt1r, N, DD, DD, 1);
    gemm_tf32<<<grid3, 256>>>(pt1c, pt1i, pt1r, w_c2, w_i2, w_r2,
                              pc2, pi2, pr2, N, DD, DD, 1);

    // 4) final projections
    {
        const int threads = 256;
        const int blocks = (N * 32 + threads - 1) / threads;
        head_final<<<blocks, threads>>>(pc2, pi2, pr2,
                                        w_c3, b_c3, w_i3, b_i3, w_r3, b_r3,
                                        out, N);
    }
}

// round 5
// speedup vs baseline: 2.3132x; 1.0358x over previous
#include <cuda_runtime.h>
#include <cstdint>

#define BB 4
#define CC 256
#define HH 256
#define WW 256
#define NROI_MAX 2048
#define FDIM 2304
#define DD 256

// ---------------- scratch ----------------------------------------------------
__device__ float g_fmt[BB * HH * WW * CC];
__device__ float g_x  [NROI_MAX * FDIM];
__device__ float g_h1 [NROI_MAX * DD];
__device__ float g_sh [NROI_MAX * DD];
__device__ float g_t1c[NROI_MAX * DD];
__device__ float g_t1i[NROI_MAX * DD];
__device__ float g_t1r[NROI_MAX * DD];
__device__ float g_c2 [NROI_MAX * DD];
__device__ float g_i2 [NROI_MAX * DD];
__device__ float g_r2 [NROI_MAX * DD];

// ---------------- NCHW -> NHWC transpose (64c x 64s per block) --------------
__global__ __launch_bounds__(256)
void transpose_kernel(const float* __restrict__ fm, float* __restrict__ fmt)
{
    __shared__ float tile[64][65];

    const int b  = blockIdx.z;
    const int s0 = blockIdx.x * 64;
    const int c0 = blockIdx.y * 64;
    const int t  = threadIdx.x;

#pragma unroll
    for (int l = 0; l < 4; l++) {
        const int slot = t + l * 256;
        const int ci = slot >> 4;          // 0..63
        const int s4 = (slot & 15) * 4;    // 0..60
        const float4 v = *(const float4*)(fm +
            ((size_t)b * CC + (c0 + ci)) * (size_t)(HH * WW) + s0 + s4);
        tile[ci][s4 + 0] = v.x;
        tile[ci][s4 + 1] = v.y;
        tile[ci][s4 + 2] = v.z;
        tile[ci][s4 + 3] = v.w;
    }
    __syncthreads();

#pragma unroll
    for (int l = 0; l < 4; l++) {
        const int slot = t + l * 256;
        const int si = slot >> 4;          // 0..63
        const int c4 = (slot & 15) * 4;    // 0..60
        float4 v;
        v.x = tile[c4 + 0][si];
        v.y = tile[c4 + 1][si];
        v.z = tile[c4 + 2][si];
        v.w = tile[c4 + 3][si];
        *(float4*)(fmt + ((size_t)b * (HH * WW) + s0 + si) * (size_t)CC + c0 + c4) = v;
    }
}

// ---------------- RoIAlignRotated (NHWC gather, float4) --------------------
// grid: N blocks, 64 threads (each thread = 4 consecutive channels).
__global__ __launch_bounds__(64)
void roi_kernel(const float* __restrict__ fmt,
                const float* __restrict__ boxes,
                const int*   __restrict__ bidx,
                float* __restrict__ xout)
{
    const int n = blockIdx.x;
    const int t = threadIdx.x;

    __shared__ int   s_o[36][4];
    __shared__ float s_w[36][4];

    if (t < 36) {
        const float gw = (float)(102.4 / 256.0);
        const float bx  = boxes[n*7 + 0];
        const float by  = boxes[n*7 + 1];
        const float rh  = boxes[n*7 + 4] / gw;
        const float rw  = boxes[n*7 + 5] / gw;
        const float ang = boxes[n*7 + 6];

        const float cx = (bx + 51.2f) / gw - 0.5f;
        const float cy = (by + 51.2f) / gw - 0.5f;
        const float ct = cosf(-ang);
        const float st = sinf(-ang);
        const float bin_h = rh / 3.0f;
        const float bin_w = rw / 3.0f;

        const int p  = t;
        const int ph = p / 12;
        const int pw = (p / 4) % 3;
        const int sy = (p >> 1) & 1;
        const int sx = p & 1;

        const float yy = -rh * 0.5f + ((float)ph + ((float)sy + 0.5f) * 0.5f) * bin_h;
        const float xx = -rw * 0.5f + ((float)pw + ((float)sx + 0.5f) * 0.5f) * bin_w;

        float y = yy * ct - xx * st + cy;
        float x = yy * st + xx * ct + cx;

        const bool valid = (y > -1.0f) && (y < (float)HH) && (x > -1.0f) && (x < (float)WW);

        y = fminf(fmaxf(y, 0.0f), (float)(HH - 1));
        x = fminf(fmaxf(x, 0.0f), (float)(WW - 1));

        int y0 = min((int)floorf(y), HH - 1);
        int x0 = min((int)floorf(x), WW - 1);
        int y1 = min(y0 + 1, HH - 1);
        int x1 = min(x0 + 1, WW - 1);

        const float ly = y - (float)y0;
        const float lx = x - (float)x0;
        const float hy = 1.0f - ly;
        const float hx = 1.0f - lx;
        const float v  = valid ? 1.0f : 0.0f;

        s_o[p][0] = (y0 * WW + x0) * CC;
        s_o[p][1] = (y0 * WW + x1) * CC;
        s_o[p][2] = (y1 * WW + x0) * CC;
        s_o[p][3] = (y1 * WW + x1) * CC;
        s_w[p][0] = hy * hx * v;
        s_w[p][1] = hy * lx * v;
        s_w[p][2] = ly * hx * v;
        s_w[p][3] = ly * lx * v;
    }
    __syncthreads();

    const int b = bidx[n];
    const float* __restrict__ base = fmt + (size_t)b * (HH * WW) * CC + t * 4;

    float4 acc[9];
#pragma unroll
    for (int i = 0; i < 9; i++) acc[i] = make_float4(0.f, 0.f, 0.f, 0.f);

#pragma unroll
    for (int p = 0; p < 36; p++) {
        const float4 v0 = *(const float4*)(base + s_o[p][0]);
        const float4 v1 = *(const float4*)(base + s_o[p][1]);
        const float4 v2 = *(const float4*)(base + s_o[p][2]);
        const float4 v3 = *(const float4*)(base + s_o[p][3]);
        const float w0 = s_w[p][0], w1 = s_w[p][1], w2 = s_w[p][2], w3 = s_w[p][3];
        float4& a = acc[p >> 2];
        a.x += w0 * v0.x + w1 * v1.x + w2 * v2.x + w3 * v3.x;
        a.y += w0 * v0.y + w1 * v1.y + w2 * v2.y + w3 * v3.y;
        a.z += w0 * v0.z + w1 * v1.z + w2 * v2.z + w3 * v3.z;
        a.w += w0 * v0.w + w1 * v1.w + w2 * v2.w + w3 * v3.w;
    }

    float* __restrict__ xo = xout + (size_t)n * FDIM + t * 4;
#pragma unroll
    for (int i = 0; i < 9; i++) {
        float4 r = acc[i];
        r.x *= 0.25f; r.y *= 0.25f; r.z *= 0.25f; r.w *= 0.25f;
        *(float4*)(xo + i * CC) = r;
    }
}

// ---------------- tf32-split tensor-core NT GEMM ----------------------------
// 3 independent accumulator sets (12 MMA chains/warp) for latency hiding.
__device__ __forceinline__ void mma_tf32(float* d, const uint32_t* a, const uint32_t* b)
{
    asm volatile(
        "mma.sync.aligned.m16n8k8.row.col.f32.tf32.tf32.f32 "
        "{%0,%1,%2,%3}, {%4,%5,%6,%7}, {%8,%9}, {%0,%1,%2,%3};\n"
        : "+f"(d[0]), "+f"(d[1]), "+f"(d[2]), "+f"(d[3])
        : "r"(a[0]), "r"(a[1]), "r"(a[2]), "r"(a[3]), "r"(b[0]), "r"(b[1]));
}

__device__ __forceinline__ void tf32_split(float f, uint32_t& hi, uint32_t& lo)
{
    uint32_t u = __float_as_uint(f);
    hi = u & 0xffffe000u;
    float l = f - __uint_as_float(hi);
    lo = __float_as_uint(l) & 0xffffe000u;
}

__device__ __forceinline__ void cp_async16(uint32_t smem_addr, const void* gptr)
{
    asm volatile("cp.async.cg.shared.global [%0], [%1], 16;\n"
                 :: "r"(smem_addr), "l"(gptr));
}

#define SKP 36

__global__ __launch_bounds__(256)
void gemm_tf32(const float* __restrict__ A0, const float* __restrict__ A1,
               const float* __restrict__ A2,
               const float* __restrict__ B0, const float* __restrict__ B1,
               const float* __restrict__ B2,
               float* __restrict__ C0, float* __restrict__ C1,
               float* __restrict__ C2,
               int M, int N, int K, int doRelu)
{
    const int bz = blockIdx.z;
    const float* __restrict__ A = (bz == 0) ? A0 : ((bz == 1) ? A1 : A2);
    const float* __restrict__ B = (bz == 0) ? B0 : ((bz == 1) ? B1 : B2);
    float* __restrict__ C       = (bz == 0) ? C0 : ((bz == 1) ? C1 : C2);

    __shared__ float sA[2][64][SKP];
    __shared__ float sB[2][64][SKP];

    const int tid  = threadIdx.x;
    const int warp = tid >> 5;
    const int lane = tid & 31;
    const int g    = lane >> 2;
    const int tg   = lane & 3;

    const int m0 = blockIdx.y * 64;
    const int n0 = blockIdx.x * 64;
    const int wm = (warp >> 1) * 16;
    const int wn = (warp & 1) * 32;

    const int lrow = tid >> 3;
    const int lk4  = (tid & 7) * 4;

    float acc[3][4][4];   // [pass][nt][frag]
#pragma unroll
    for (int ps = 0; ps < 3; ps++)
#pragma unroll
        for (int nt = 0; nt < 4; nt++)
#pragma unroll
            for (int i = 0; i < 4; i++) acc[ps][nt][i] = 0.0f;

    const int T = K >> 5;

    {
        cp_async16((uint32_t)__cvta_generic_to_shared(&sA[0][lrow     ][lk4]),
                   A + (size_t)(m0 + lrow) * K + lk4);
        cp_async16((uint32_t)__cvta_generic_to_shared(&sA[0][lrow + 32][lk4]),
                   A + (size_t)(m0 + lrow + 32) * K + lk4);
        cp_async16((uint32_t)__cvta_generic_to_shared(&sB[0][lrow     ][lk4]),
                   B + (size_t)(n0 + lrow) * K + lk4);
        cp_async16((uint32_t)__cvta_generic_to_shared(&sB[0][lrow + 32][lk4]),
                   B + (size_t)(n0 + lrow + 32) * K + lk4);
        asm volatile("cp.async.commit_group;\n");
    }

    for (int kt = 0; kt < T; kt++) {
        const int buf = kt & 1;
        if (kt + 1 < T) {
            const int nb = (kt + 1) & 1;
            const int ko = (kt + 1) << 5;
            cp_async16((uint32_t)__cvta_generic_to_shared(&sA[nb][lrow     ][lk4]),
                       A + (size_t)(m0 + lrow) * K + ko + lk4);
            cp_async16((uint32_t)__cvta_generic_to_shared(&sA[nb][lrow + 32][lk4]),
                       A + (size_t)(m0 + lrow + 32) * K + ko + lk4);
            cp_async16((uint32_t)__cvta_generic_to_shared(&sB[nb][lrow     ][lk4]),
                       B + (size_t)(n0 + lrow) * K + ko + lk4);
            cp_async16((uint32_t)__cvta_generic_to_shared(&sB[nb][lrow + 32][lk4]),
                       B + (size_t)(n0 + lrow + 32) * K + ko + lk4);
            asm volatile("cp.async.commit_group;\n");
            asm volatile("cp.async.wait_group 1;\n");
        } else {
            asm volatile("cp.async.wait_group 0;\n");
        }
        __syncthreads();

#pragma unroll
        for (int ks = 0; ks < 32; ks += 8) {
            uint32_t ah[4], al[4];
            tf32_split(sA[buf][wm + g    ][ks + tg    ], ah[0], al[0]);
            tf32_split(sA[buf][wm + g + 8][ks + tg    ], ah[1], al[1]);
            tf32_split(sA[buf][wm + g    ][ks + tg + 4], ah[2], al[2]);
            tf32_split(sA[buf][wm + g + 8][ks + tg + 4], ah[3], al[3]);

            uint32_t bh[4][2], bl[4][2];
#pragma unroll
            for (int nt = 0; nt < 4; nt++) {
                const int col = wn + nt * 8 + g;
                tf32_split(sB[buf][col][ks + tg    ], bh[nt][0], bl[nt][0]);
                tf32_split(sB[buf][col][ks + tg + 4], bh[nt][1], bl[nt][1]);
            }
#pragma unroll
            for (int nt = 0; nt < 4; nt++) {
                mma_tf32(acc[0][nt], ah, bh[nt]);
                mma_tf32(acc[1][nt], ah, bl[nt]);
                mma_tf32(acc[2][nt], al, bh[nt]);
            }
        }
        __syncthreads();
    }

    const int r0 = m0 + wm + g;
    const int r1 = r0 + 8;
#pragma unroll
    for (int nt = 0; nt < 4; nt++) {
        const int col = n0 + wn + nt * 8 + 2 * tg;
        float s0 = acc[0][nt][0] + acc[1][nt][0] + acc[2][nt][0];
        float s1 = acc[0][nt][1] + acc[1][nt][1] + acc[2][nt][1];
        float s2 = acc[0][nt][2] + acc[1][nt][2] + acc[2][nt][2];
        float s3 = acc[0][nt][3] + acc[1][nt][3] + acc[2][nt][3];
        if (doRelu) {
            s0 = fmaxf(s0, 0.0f); s1 = fmaxf(s1, 0.0f);
            s2 = fmaxf(s2, 0.0f); s3 = fmaxf(s3, 0.0f);
        }
        *(float2*)&C[(size_t)r0 * N + col] = make_float2(s0, s1);
        *(float2*)&C[(size_t)r1 * N + col] = make_float2(s2, s3);
    }
}

// ---------------- fused head-final projections -----------------------------
__global__ void head_final(const float* __restrict__ c2,
                           const float* __restrict__ i2,
                           const float* __restrict__ r2,
                           const float* __restrict__ wc, const float* __restrict__ bc,
                           const float* __restrict__ wi, const float* __restrict__ bi,
                           const float* __restrict__ wr, const float* __restrict__ br,
                           float* __restrict__ out, int N)
{
    const int warp = (blockIdx.x * blockDim.x + threadIdx.x) >> 5;
    const int lane = threadIdx.x & 31;
    if (warp >= N) return;

    float sc = 0.0f, si = 0.0f;
    float sr[7];
#pragma unroll
    for (int j = 0; j < 7; j++) sr[j] = 0.0f;

    const float* tc = c2 + (size_t)warp * DD;
    const float* ti = i2 + (size_t)warp * DD;
    const float* tr = r2 + (size_t)warp * DD;

#pragma unroll
    for (int kk = 0; kk < DD / 32; kk++) {
        const int k = lane + kk * 32;
        const float vc = tc[k], vi = ti[k], vr = tr[k];
        sc += vc * wc[k];
        si += vi * wi[k];
#pragma unroll
        for (int j = 0; j < 7; j++) sr[j] += vr * wr[j * DD + k];
    }

#pragma unroll
    for (int off = 16; off > 0; off >>= 1) {
        sc += __shfl_down_sync(0xffffffffu, sc, off);
        si += __shfl_down_sync(0xffffffffu, si, off);
#pragma unroll
        for (int j = 0; j < 7; j++) sr[j] += __shfl_down_sync(0xffffffffu, sr[j], off);
    }

    if (lane == 0) {
        out[warp]     = sc + bc[0];
        out[N + warp] = si + bi[0];
#pragma unroll
        for (int j = 0; j < 7; j++)
            out[2 * N + warp * 7 + j] = sr[j] + br[j];
    }
}

// ---------------- launch ----------------------------------------------------
extern "C" void kernel_launch(void* const* d_in, const int* in_sizes, int n_in,
                              void* d_out, int out_size)
{
    const float* fm    = (const float*)d_in[0];
    const float* boxes = (const float*)d_in[1];
    const int*   bidx  = (const int*)  d_in[2];
    const float* w_sh1 = (const float*)d_in[3];
    const float* w_sh2 = (const float*)d_in[4];
    const float* w_c1  = (const float*)d_in[5];
    const float* w_c2  = (const float*)d_in[6];
    const float* w_c3  = (const float*)d_in[7];
    const float* b_c3  = (const float*)d_in[8];
    const float* w_i1  = (const float*)d_in[9];
    const float* w_i2  = (const float*)d_in[10];
    const float* w_i3  = (const float*)d_in[11];
    const float* b_i3  = (const float*)d_in[12];
    const float* w_r1  = (const float*)d_in[13];
    const float* w_r2  = (const float*)d_in[14];
    const float* w_r3  = (const float*)d_in[15];
    const float* b_r3  = (const float*)d_in[16];
    float* out = (float*)d_out;

    const int N = in_sizes[2];

    float *pfmt, *px, *ph1, *psh, *pt1c, *pt1i, *pt1r, *pc2, *pi2, *pr2;
    cudaGetSymbolAddress((void**)&pfmt, g_fmt);
    cudaGetSymbolAddress((void**)&px,   g_x);
    cudaGetSymbolAddress((void**)&ph1,  g_h1);
    cudaGetSymbolAddress((void**)&psh,  g_sh);
    cudaGetSymbolAddress((void**)&pt1c, g_t1c);
    cudaGetSymbolAddress((void**)&pt1i, g_t1i);
    cudaGetSymbolAddress((void**)&pt1r, g_t1r);
    cudaGetSymbolAddress((void**)&pc2,  g_c2);
    cudaGetSymbolAddress((void**)&pi2,  g_i2);
    cudaGetSymbolAddress((void**)&pr2,  g_r2);

    // 0) NCHW -> NHWC
    {
        dim3 grid(HH * WW / 64, CC / 64, BB);
        transpose_kernel<<<grid, 256>>>(fm, pfmt);
    }

    // 1) RoIAlignRotated -> x [N, 2304]
    roi_kernel<<<N, 64>>>(pfmt, boxes, bidx, px);

    // 2) trunk GEMMs
    dim3 grid1(DD / 64, N / 64, 1);
    gemm_tf32<<<grid1, 256>>>(px, px, px, w_sh1, w_sh1, w_sh1,
                              ph1, ph1, ph1, N, DD, FDIM, 1);
    gemm_tf32<<<grid1, 256>>>(ph1, ph1, ph1, w_sh2, w_sh2, w_sh2,
                              psh, psh, psh, N, DD, DD, 1);

    // 3) heads, batched over z
    dim3 grid3(DD / 64, N / 64, 3);
    gemm_tf32<<<grid3, 256>>>(psh, psh, psh, w_c1, w_i1, w_r1,
                              pt1c, pt1i, pt1r, N, DD, DD, 1);
    gemm_tf32<<<grid3, 256>>>(pt1c, pt1i, pt1r, w_c2, w_i2, w_r2,
                              pc2, pi2, pr2, N, DD, DD, 1);

    // 4) final projections
    {
        const int threads = 256;
        const int blocks = (N * 32 + threads - 1) / threads;
        head_final<<<blocks, threads>>>(pc2, pi2, pr2,
                                        w_c3, b_c3, w_i3, b_i3, w_r3, b_r3,
                                        out, N);
    }
}